// round 16
// baseline (speedup 1.0000x reference)
#include <cuda_runtime.h>
#include <stdint.h>

// Shapes (fixed by the problem): k (1,32,64,256,256) fp32, mask (64,256,256) int32
// mask values are exactly {0,1} (jax randint(0,2)) — the byte-packing below relies on this.
#define ALPHA 0.5f
#define BETA  0.25f

constexpr int NC = 32;
constexpr int NT = 64;
constexpr int NX = 256;
constexpr int NY = 256;
constexpr int SPATIAL = NX * NY;              // 65536 elems per t-slice
constexpr int SPAT4   = SPATIAL / 4;          // 16384 int4 per t-slice
constexpr long PLANE  = (long)NT * SPATIAL;   // elems per channel
constexpr int NY4     = NY / 4;               // 64 float4 per row
constexpr int TOTAL_COLS = NC * NX * NY4;     // 524288 column tasks

// Pack an int4 of {0,1} mask values into one uint: byte b holds component b.
__device__ __forceinline__ unsigned pack01(int4 m) {
    return (unsigned)m.x | ((unsigned)m.y << 8) | ((unsigned)m.z << 16) | ((unsigned)m.w << 24);
}

// Per-element select from packed predicate words (bit-test at bits 0/8/16/24):
//   mc byte set   -> k[t]
//   selp byte set -> ALPHA * k[t-1]   (prev & !cur)
//   seln byte set -> BETA  * k[t+1]   (next & !prev & !cur)
//   else          -> 0
__device__ __forceinline__ float4 sel_apply(unsigned mc, unsigned selp, unsigned seln,
                                            float4 kp, float4 kc, float4 kn) {
    float4 o;
    o.x = (mc & 0x1u)        ? kc.x : (selp & 0x1u)        ? ALPHA * kp.x : (seln & 0x1u)        ? BETA * kn.x : 0.f;
    o.y = (mc & 0x100u)      ? kc.y : (selp & 0x100u)      ? ALPHA * kp.y : (seln & 0x100u)      ? BETA * kn.y : 0.f;
    o.z = (mc & 0x10000u)    ? kc.z : (selp & 0x10000u)    ? ALPHA * kp.z : (seln & 0x10000u)    ? BETA * kn.z : 0.f;
    o.w = (mc & 0x1000000u)  ? kc.w : (selp & 0x1000000u)  ? ALPHA * kp.w : (seln & 0x1000000u)  ? BETA * kn.w : 0.f;
    return o;
}

// ---------------------------------------------------------------------------
// Single fused kernel (R11 apply structure + inline mask logic).
// Each thread owns (c, x, 4 consecutive y) and walks t with register-carried
// kp/kc/kn float4 AND packed mask words mp/mc -> every k element read exactly
// once, mask read from L2 (16 MiB, resident across all 32 channel sweeps).
// Streaming hints (.cs) on k/out keep L2 reserved for the mask.
// ---------------------------------------------------------------------------
__global__ __launch_bounds__(256, 8)
void fused_kernel(const float* __restrict__ k, const int* __restrict__ mask,
                  float* __restrict__ out) {
    int tid = blockIdx.x * blockDim.x + threadIdx.x;  // over TOTAL_COLS (exact multiple)

    // All powers of two: shifts/masks only.
    int y4 = tid & (NY4 - 1);          // tid % 64
    int x  = (tid >> 6) & (NX - 1);    // (tid / 64) % 256
    int c  = tid >> 14;                // tid / (64*256)

    int  soff = (x << 8) + (y4 << 2);                 // spatial element offset (mult of 4)
    long base = (long)c * PLANE + soff;               // k/out element index @ t=0

    const float* pk = k + base;
    float*       po = out + base;
    const int4*  pm = reinterpret_cast<const int4*>(mask) + (soff >> 2);

    float4   kp = make_float4(0.f, 0.f, 0.f, 0.f);
    float4   kc = __ldcs(reinterpret_cast<const float4*>(pk));
    unsigned mp = 0u;                                 // t=-1 padding
    unsigned mc = pack01(pm[0]);

    // Main loop: t = 0 .. NT-2 always has valid t+1 loads (no branch).
    #pragma unroll 4
    for (int t = 0; t < NT - 1; ++t) {
        float4   kn = __ldcs(reinterpret_cast<const float4*>(pk + (t + 1) * SPATIAL));
        unsigned mn = pack01(pm[(t + 1) * SPAT4]);    // L2-resident

        unsigned selp = mp & ~mc;                     // prev-only (bytes are 0/1)
        unsigned seln = mn & ~(mp | mc);              // next & !prev & !cur

        float4 o = sel_apply(mc, selp, seln, kp, kc, kn);
        __stcs(reinterpret_cast<float4*>(po + t * SPATIAL), o);

        kp = kc;  kc = kn;
        mp = mc;  mc = mn;
    }

    // Epilogue t = NT-1: next is zero-padded (seln = 0, kn unused).
    {
        unsigned selp = mp & ~mc;
        float4 o = sel_apply(mc, selp, 0u, kp, kc, kc);
        __stcs(reinterpret_cast<float4*>(po + (NT - 1) * SPATIAL), o);
    }
}

extern "C" void kernel_launch(void* const* d_in, const int* in_sizes, int n_in,
                              void* d_out, int out_size) {
    const float* k    = (const float*)d_in[0];
    const int*   mask = (const int*)d_in[1];
    float*       out  = (float*)d_out;

    fused_kernel<<<TOTAL_COLS / 256, 256>>>(k, mask, out);   // 2048 x 256 (R11 geometry)
}

// round 17
// speedup vs baseline: 1.0894x; 1.0894x over previous
#include <cuda_runtime.h>
#include <stdint.h>

// Shapes (fixed by the problem): k (1,32,64,256,256) fp32, mask (64,256,256) int32
#define ALPHA 0.5f
#define BETA  0.25f

constexpr int NC = 32;
constexpr int NT = 64;
constexpr int NX = 256;
constexpr int NY = 256;
constexpr int SPATIAL = NX * NY;              // 65536 elems per t-slice
constexpr int SPAT4   = SPATIAL / 4;          // 16384 int4 per t-slice
constexpr int SPATB   = SPATIAL / 4;          // 16384 selector BYTES per t-slice (2 bits/site)
constexpr long PLANE  = (long)NT * SPATIAL;   // elems per channel
constexpr int NY4     = NY / 4;               // 64 float4 per row
constexpr int TOTAL_COLS = NC * NX * NY4;     // 524288 column tasks

// 1 MiB selector scratch, 2 bits per site (4 sites per byte):
//   0 = zero, 1 = k[t], 2 = ALPHA*k[t-1], 3 = BETA*k[t+1]
__device__ unsigned char g_sel2[NT * SPATIAL / 4];

// ---------------------------------------------------------------------------
// Kernel 1: mask (64,256,256) int32 -> packed 2-bit selector.
// Each thread handles 16 sites (4x int4 loads per of cur/prev/next) and
// stores one uint (4 selector bytes). blockIdx.y = t.
//   m_cur                          -> 1  (k)
//   !m_cur & m_prev                -> 2  (ALPHA*k_prev)
//   m_next & !(m_prev | m_cur)     -> 3  (BETA*k_next)
// (mutually exclusive by construction)
// ---------------------------------------------------------------------------
__device__ __forceinline__ unsigned sel_byte(int4 cur, int4 prev, int4 next) {
    unsigned s0 = cur.x ? 1u : (prev.x ? 2u : (next.x ? 3u : 0u));
    unsigned s1 = cur.y ? 1u : (prev.y ? 2u : (next.y ? 3u : 0u));
    unsigned s2 = cur.z ? 1u : (prev.z ? 2u : (next.z ? 3u : 0u));
    unsigned s3 = cur.w ? 1u : (prev.w ? 2u : (next.w ? 3u : 0u));
    return s0 | (s1 << 2) | (s2 << 4) | (s3 << 6);
}

__global__ __launch_bounds__(256)
void sel_kernel(const int4* __restrict__ mask) {
    int t = blockIdx.y;
    int i = blockIdx.x * blockDim.x + threadIdx.x;   // 0 .. SPATIAL/16 - 1
    int idx4 = t * SPAT4 + i * 4;                    // first int4 of this thread's 16 sites

    unsigned w = 0;
    #pragma unroll
    for (int j = 0; j < 4; ++j) {
        int4 cur  = mask[idx4 + j];
        int4 prev = (t > 0)      ? mask[idx4 + j - SPAT4] : make_int4(0, 0, 0, 0);
        int4 next = (t < NT - 1) ? mask[idx4 + j + SPAT4] : make_int4(0, 0, 0, 0);
        w |= sel_byte(cur, prev, next) << (8 * j);
    }
    reinterpret_cast<unsigned*>(g_sel2)[t * (SPATB / 4) + i] = w;
}

// ---------------------------------------------------------------------------
// Kernel 2: flat 1-column-per-thread mapping (R11 geometry, best measured).
// Each thread owns (c, x, 4 consecutive y) and walks t with register-carried
// kp/kc/kn float4. Selector read is ONE BYTE per iteration (4x less L1/L2
// traffic than R11's uchar4 — R16 showed per-iter mask-load bytes directly
// gate DRAM%). k/out use .cs streaming; selector (1 MiB) stays L2-resident.
// ---------------------------------------------------------------------------
__device__ __forceinline__ float4 sel_apply(unsigned b, float4 kp, float4 kc, float4 kn) {
    unsigned s0 =  b        & 3u;
    unsigned s1 = (b >> 2)  & 3u;
    unsigned s2 = (b >> 4)  & 3u;
    unsigned s3 = (b >> 6)  & 3u;
    float4 o;
    o.x = (s0 == 1) ? kc.x : (s0 == 2) ? ALPHA * kp.x : (s0 == 3) ? BETA * kn.x : 0.f;
    o.y = (s1 == 1) ? kc.y : (s1 == 2) ? ALPHA * kp.y : (s1 == 3) ? BETA * kn.y : 0.f;
    o.z = (s2 == 1) ? kc.z : (s2 == 2) ? ALPHA * kp.z : (s2 == 3) ? BETA * kn.z : 0.f;
    o.w = (s3 == 1) ? kc.w : (s3 == 2) ? ALPHA * kp.w : (s3 == 3) ? BETA * kn.w : 0.f;
    return o;
}

__global__ __launch_bounds__(256, 8)
void apply_kernel(const float* __restrict__ k, float* __restrict__ out) {
    int tid = blockIdx.x * blockDim.x + threadIdx.x;  // over TOTAL_COLS (exact multiple)

    // All powers of two: shifts/masks only.
    int y4 = tid & (NY4 - 1);          // tid % 64
    int x  = (tid >> 6) & (NX - 1);    // (tid / 64) % 256
    int c  = tid >> 14;                // tid / (64*256)

    long base   = (long)c * PLANE + (long)x * NY + (long)y4 * 4; // k/out index @ t=0
    int  sbase  = x * NY4 + y4;                                  // selector BYTE index @ t=0

    const float* pk = k + base;
    float*       po = out + base;

    float4 kp = make_float4(0.f, 0.f, 0.f, 0.f);
    float4 kc = __ldcs(reinterpret_cast<const float4*>(pk));

    // Main loop: t = 0 .. NT-2 always has a valid t+1 load (no branch).
    #pragma unroll 4
    for (int t = 0; t < NT - 1; ++t) {
        float4   kn = __ldcs(reinterpret_cast<const float4*>(pk + (t + 1) * SPATIAL));
        unsigned b  = g_sel2[sbase + t * SPATB];      // 1-byte selector, L2-resident
        float4   o  = sel_apply(b, kp, kc, kn);
        __stcs(reinterpret_cast<float4*>(po + t * SPATIAL), o);
        kp = kc;
        kc = kn;
    }

    // Epilogue t = NT-1: k_next is zero-padded (sel 3 never fires meaningfully).
    {
        const int t = NT - 1;
        unsigned b = g_sel2[sbase + t * SPATB];
        float4   o = sel_apply(b, kp, kc, make_float4(0.f, 0.f, 0.f, 0.f));
        __stcs(reinterpret_cast<float4*>(po + t * SPATIAL), o);
    }
}

extern "C" void kernel_launch(void* const* d_in, const int* in_sizes, int n_in,
                              void* d_out, int out_size) {
    const float* k    = (const float*)d_in[0];
    const int*   mask = (const int*)d_in[1];
    float*       out  = (float*)d_out;

    // Kernel 1: packed 2-bit selector (1 MiB)
    {
        dim3 grid(SPATIAL / 16 / 256, NT);   // (16, 64)
        sel_kernel<<<grid, 256>>>(reinterpret_cast<const int4*>(mask));
    }

    // Kernel 2: streaming apply (R11 geometry: 2048 x 256)
    {
        apply_kernel<<<TOTAL_COLS / 256, 256>>>(k, out);
    }
}